// round 1
// baseline (speedup 1.0000x reference)
#include <cuda_runtime.h>
#include <cstdint>

#define N_PATCH 50000
#define DIM     2048
#define HID     512
#define KSEL    5000      // max(1, int(50000*0.1))
#define CAP     8192      // candidate capacity (pow2 for bitonic)

// ---------------- scratch (static device globals: allocation-free) ----------
__device__ float              g_A[N_PATCH];
__device__ float              g_maxval;
__device__ unsigned           g_hist[256];
__device__ unsigned           g_prefix;
__device__ unsigned           g_mask;
__device__ int                g_krem;
__device__ int                g_cand_cnt;
__device__ int                g_cand_idx[CAP];
__device__ unsigned long long g_skey[CAP];
__device__ int                g_top_idx[KSEL];
__device__ float              g_ak[KSEL];
__device__ float              g_partial[32 * DIM];

__device__ __forceinline__ unsigned f2k(float f) {
    unsigned u = __float_as_uint(f);
    return (u & 0x80000000u) ? ~u : (u | 0x80000000u);  // monotone float->uint
}

// ---------------- Stage 1: fused GEMM + tanh + W2 reduce --------------------
// A[i] = b2 + sum_j W2[j] * tanh( x[i,:] . W1[j,:] + b1[j] )
#define BM 64
#define BN 512
#define BK 16

__global__ void __launch_bounds__(256, 1)
gemm_score_kernel(const float* __restrict__ x,  const float* __restrict__ W1,
                  const float* __restrict__ b1, const float* __restrict__ W2,
                  const float* __restrict__ b2)
{
    __shared__ float As[BK][68];    // padded: 2-way max store conflicts, f4-aligned rows
    __shared__ float Bs[BK][516];

    const int tid = threadIdx.x;
    const int tx  = tid & 31;       // column group (32 lanes)
    const int ty  = tid >> 5;       // row group (8 groups of 8 rows)
    const int mBase = blockIdx.x * BM;

    float c[8][16];
#pragma unroll
    for (int r = 0; r < 8; r++)
#pragma unroll
        for (int q = 0; q < 16; q++) c[r][q] = 0.f;

    // x tile loader mapping: thread -> one float4 (64 rows x 4 f4)
    const int arow = tid >> 2;
    const int akk  = (tid & 3) * 4;
    int gr = mBase + arow;
    if (gr >= N_PATCH) gr = N_PATCH - 1;
    const float* xrow = x + (size_t)gr * DIM;

    for (int k0 = 0; k0 < DIM; k0 += BK) {
        // load x tile (transposed into As[k][m])
        float4 av = *reinterpret_cast<const float4*>(xrow + k0 + akk);
        As[akk + 0][arow] = av.x;  As[akk + 1][arow] = av.y;
        As[akk + 2][arow] = av.z;  As[akk + 3][arow] = av.w;
        // load W1 tile (512 rows x 4 f4 -> Bs[k][n]), 8 f4 per thread
#pragma unroll
        for (int j = 0; j < 8; j++) {
            int f   = tid + j * 256;
            int n   = f >> 2;
            int kk4 = (f & 3) * 4;
            float4 bv = *reinterpret_cast<const float4*>(W1 + (size_t)n * DIM + k0 + kk4);
            Bs[kk4 + 0][n] = bv.x;  Bs[kk4 + 1][n] = bv.y;
            Bs[kk4 + 2][n] = bv.z;  Bs[kk4 + 3][n] = bv.w;
        }
        __syncthreads();

#pragma unroll
        for (int kk = 0; kk < BK; kk++) {
            float4 a0 = *reinterpret_cast<const float4*>(&As[kk][ty * 8]);
            float4 a1 = *reinterpret_cast<const float4*>(&As[kk][ty * 8 + 4]);
            float a[8] = {a0.x, a0.y, a0.z, a0.w, a1.x, a1.y, a1.z, a1.w};
            float b[16];
#pragma unroll
            for (int j = 0; j < 4; j++) {
                float4 bv = *reinterpret_cast<const float4*>(&Bs[kk][j * 128 + tx * 4]);
                b[j * 4 + 0] = bv.x;  b[j * 4 + 1] = bv.y;
                b[j * 4 + 2] = bv.z;  b[j * 4 + 3] = bv.w;
            }
#pragma unroll
            for (int r = 0; r < 8; r++)
#pragma unroll
                for (int q = 0; q < 16; q++) c[r][q] = fmaf(a[r], b[q], c[r][q]);
        }
        __syncthreads();
    }

    // epilogue: tanh + W2 reduce across the 512 columns (warp owns all cols)
    const float b2v = b2[0];
#pragma unroll
    for (int r = 0; r < 8; r++) {
        float s = 0.f;
#pragma unroll
        for (int j = 0; j < 4; j++)
#pragma unroll
            for (int q = 0; q < 4; q++) {
                int col = j * 128 + tx * 4 + q;
                s += W2[col] * tanhf(c[r][j * 4 + q] + b1[col]);
            }
#pragma unroll
        for (int o = 16; o > 0; o >>= 1) s += __shfl_xor_sync(0xFFFFFFFFu, s, o);
        int row = mBase + ty * 8 + r;
        if (tx == 0 && row < N_PATCH) g_A[row] = s + b2v;
    }
}

// ---------------- Stage 2: global max --------------------------------------
__global__ void max_kernel() {
    __shared__ float red[1024];
    float m = -1e30f;
    for (int i = threadIdx.x; i < N_PATCH; i += 1024) m = fmaxf(m, g_A[i]);
    red[threadIdx.x] = m;
    __syncthreads();
    for (int o = 512; o > 0; o >>= 1) {
        if (threadIdx.x < o) red[threadIdx.x] = fmaxf(red[threadIdx.x], red[threadIdx.x + o]);
        __syncthreads();
    }
    if (threadIdx.x == 0) g_maxval = red[0];
}

// ---------------- Stage 3: radix-select threshold (k-th largest) -----------
__global__ void init_kernel() {
    int t = threadIdx.x;
    g_hist[t] = 0;
    if (t == 0) { g_prefix = 0; g_mask = 0; g_krem = KSEL; g_cand_cnt = 0; }
}

__global__ void hist_kernel(int shift) {
    __shared__ unsigned h[256];
    h[threadIdx.x] = 0;
    __syncthreads();
    const unsigned mask = g_mask, pref = g_prefix;
    for (int i = blockIdx.x * blockDim.x + threadIdx.x; i < N_PATCH;
         i += gridDim.x * blockDim.x) {
        unsigned key = f2k(g_A[i]);
        if ((key & mask) == pref) atomicAdd(&h[(key >> shift) & 255u], 1u);
    }
    __syncthreads();
    if (h[threadIdx.x]) atomicAdd(&g_hist[threadIdx.x], h[threadIdx.x]);
}

__global__ void scan_kernel(int shift) {
    if (threadIdx.x == 0) {
        int krem = g_krem;
        unsigned cum = 0;
        int sel = 0;
        for (int b = 255; b >= 0; b--) {
            unsigned hb = g_hist[b];
            cum += hb;
            if (cum >= (unsigned)krem) { sel = b; g_krem = krem - (int)(cum - hb); break; }
        }
        g_prefix |= ((unsigned)sel) << shift;
        g_mask   |= 0xFFu << shift;
    }
    __syncthreads();
    g_hist[threadIdx.x] = 0;  // ready for next pass
}

__global__ void compact_kernel() {
    const unsigned thr = g_prefix;  // full key of k-th largest after 4 passes
    for (int i = blockIdx.x * blockDim.x + threadIdx.x; i < N_PATCH;
         i += gridDim.x * blockDim.x) {
        if (f2k(g_A[i]) >= thr) {
            int p = atomicAdd(&g_cand_cnt, 1);
            if (p < CAP) g_cand_idx[p] = i;
        }
    }
}

// ---------------- Stage 4: sort candidates (val desc, idx asc) --------------
// Bitonic over global key64 = (monotone_key << 32) | (0xFFFFFFFF - idx).
__global__ void sort_kernel() {
    int cnt = g_cand_cnt;
    if (cnt > CAP) cnt = CAP;
    for (int i = threadIdx.x; i < CAP; i += blockDim.x) {
        if (i < cnt) {
            int idx = g_cand_idx[i];
            g_skey[i] = ((unsigned long long)f2k(g_A[idx]) << 32) |
                        (unsigned long long)(0xFFFFFFFFu - (unsigned)idx);
        } else {
            g_skey[i] = 0ull;  // below any real key
        }
    }
    __syncthreads();
    for (int k = 2; k <= CAP; k <<= 1) {
        for (int j = k >> 1; j > 0; j >>= 1) {
            for (int i = threadIdx.x; i < CAP; i += blockDim.x) {
                int ixj = i ^ j;
                if (ixj > i) {
                    unsigned long long va = g_skey[i], vb = g_skey[ixj];
                    bool up = ((i & k) == 0);
                    if (up ? (va < vb) : (va > vb)) { g_skey[i] = vb; g_skey[ixj] = va; }
                }
            }
            __syncthreads();
        }
    }
    for (int i = threadIdx.x; i < KSEL; i += blockDim.x)
        g_top_idx[i] = (int)(0xFFFFFFFFu - (unsigned)(g_skey[i] & 0xFFFFFFFFull));
}

// ---------------- Stage 5: Ak = exp(A-max)/sum_topk ------------------------
__global__ void expnorm_kernel(float* __restrict__ out) {
    __shared__ float red[1024];
    const float mx = g_maxval;
    float p = 0.f;
    for (int i = threadIdx.x; i < KSEL; i += 1024)
        p += expf(g_A[g_top_idx[i]] - mx);
    red[threadIdx.x] = p;
    __syncthreads();
    for (int o = 512; o > 0; o >>= 1) {
        if (threadIdx.x < o) red[threadIdx.x] += red[threadIdx.x + o];
        __syncthreads();
    }
    const float S = red[0];
    for (int i = threadIdx.x; i < KSEL; i += 1024) {
        float ak = expf(g_A[g_top_idx[i]] - mx) / S;
        g_ak[i] = ak;
        out[DIM + i] = ak;   // Ak output, sorted desc like jax top_k
    }
}

// ---------------- Stage 6: M = sum Ak_i * x[idx_i] (deterministic 2-stage) --
__global__ void wsum_kernel(const float* __restrict__ x) {
    int col = blockIdx.x * 256 + threadIdx.x;
    int r0  = blockIdx.y;
    float acc = 0.f;
    for (int r = r0; r < KSEL; r += 32)
        acc += g_ak[r] * x[(size_t)g_top_idx[r] * DIM + col];
    g_partial[r0 * DIM + col] = acc;
}

__global__ void final_kernel(float* __restrict__ out) {
    int col = blockIdx.x * 256 + threadIdx.x;
    float s = 0.f;
#pragma unroll
    for (int r = 0; r < 32; r++) s += g_partial[r * DIM + col];
    out[col] = s;
}

// ---------------- launch ----------------------------------------------------
extern "C" void kernel_launch(void* const* d_in, const int* in_sizes, int n_in,
                              void* d_out, int out_size)
{
    const float* x  = (const float*)d_in[0];
    const float* W1 = (const float*)d_in[1];
    const float* b1 = (const float*)d_in[2];
    const float* W2 = (const float*)d_in[3];
    const float* b2 = (const float*)d_in[4];
    float* out = (float*)d_out;
    (void)in_sizes; (void)n_in; (void)out_size;

    gemm_score_kernel<<<(N_PATCH + BM - 1) / BM, 256>>>(x, W1, b1, W2, b2);
    max_kernel<<<1, 1024>>>();
    init_kernel<<<1, 256>>>();
    for (int s = 24; s >= 0; s -= 8) {
        hist_kernel<<<256, 256>>>(s);
        scan_kernel<<<1, 256>>>(s);
    }
    compact_kernel<<<256, 256>>>();
    sort_kernel<<<1, 1024>>>();
    expnorm_kernel<<<1, 1024>>>(out);
    wsum_kernel<<<dim3(8, 32), 256>>>(x);
    final_kernel<<<8, 256>>>(out);
}

// round 5
// speedup vs baseline: 1.7139x; 1.7139x over previous
#include <cuda_runtime.h>
#include <cstdint>

#define N_PATCH 50000
#define DIM     2048
#define HID     512
#define KSEL    5000      // max(1, int(50000*0.1))
#define CAP     8192      // candidate capacity (pow2 for bitonic)

// ---- mma.sync GEMM tiling ----
#define BM     128
#define BN     128
#define KC     16
#define KSTR   20                       // padded words per row (bank = (4m+k)&31 = lane)
#define NUM_KC (DIM / KC)               // 128
#define MBLK   ((N_PATCH + BM - 1) / BM)   // 391
#define NBLK   (HID / BN)                  // 4
#define GRID1  (MBLK * NBLK)               // 1564

#define TILE_W   (128 * KSTR)              // 2560 words per tile
#define STAGE_W  (2 * TILE_W)              // A + B
#define SM_RED   (2 * STAGE_W)             // 10240: red[128][4]
#define SM_W2    (SM_RED + 512)            // 10752
#define SM_B1    (SM_W2 + 128)             // 10880
#define SM_WORDS (SM_B1 + 128)             // 11008 floats = 44032 B (static ok)

// ---------------- scratch (static device globals: allocation-free) ----------
__device__ float              g_Apart[NBLK][50048];
__device__ float              g_A[N_PATCH];
__device__ float              g_maxval;
__device__ unsigned           g_hist[256];
__device__ unsigned           g_prefix;
__device__ unsigned           g_mask;
__device__ int                g_krem;
__device__ int                g_cand_cnt;
__device__ int                g_cand_idx[CAP];
__device__ unsigned long long g_skey[CAP];
__device__ int                g_top_idx[KSEL];
__device__ float              g_ak[KSEL];
__device__ float              g_partial[32 * DIM];

// ---------------- helpers ----------------------------------------------------
__device__ __forceinline__ uint32_t smem_u32(const void* p) {
    uint32_t a;
    asm("{ .reg .u64 t; cvta.to.shared.u64 t, %1; cvt.u32.u64 %0, t; }" : "=r"(a) : "l"(p));
    return a;
}
__device__ __forceinline__ void cpa16(uint32_t saddr, const void* g) {
    asm volatile("cp.async.cg.shared.global [%0], [%1], 16;" :: "r"(saddr), "l"(g));
}
__device__ __forceinline__ void split2(float v, uint32_t& h, uint32_t& l) {
    uint32_t hb = __float_as_uint(v) & 0xFFFFE000u;   // tf32-visible bits
    h = hb;
    l = __float_as_uint(v - __uint_as_float(hb));     // HW truncates lo's tail
}
__device__ __forceinline__ void mma_tf32(float* d, uint32_t a0, uint32_t a1,
                                         uint32_t a2, uint32_t a3,
                                         uint32_t b0, uint32_t b1) {
    asm volatile("mma.sync.aligned.m16n8k8.row.col.f32.tf32.tf32.f32 "
                 "{%0,%1,%2,%3}, {%4,%5,%6,%7}, {%8,%9}, {%0,%1,%2,%3};"
                 : "+f"(d[0]), "+f"(d[1]), "+f"(d[2]), "+f"(d[3])
                 : "r"(a0), "r"(a1), "r"(a2), "r"(a3), "r"(b0), "r"(b1));
}
__device__ __forceinline__ unsigned f2k(float f) {
    unsigned u = __float_as_uint(f);
    return (u & 0x80000000u) ? ~u : (u | 0x80000000u);
}

// ---------------- Stage 1: 3xTF32 mma.sync GEMM + tanh + W2 partial ---------
__global__ void __launch_bounds__(256, 2)
mma_score_kernel(const float* __restrict__ x,  const float* __restrict__ W1,
                 const float* __restrict__ b1, const float* __restrict__ W2)
{
    __shared__ float sm[SM_WORDS];
    const int tid   = threadIdx.x;
    const int lane  = tid & 31;
    const int wid   = tid >> 5;
    const int warpM = wid & 1;           // 2 groups of 64 rows
    const int warpN = wid >> 1;          // 4 groups of 32 cols
    const int mblk  = blockIdx.x >> 2;
    const int nblk  = blockIdx.x & 3;
    const int m_base = mblk * BM;
    const int n_base = nblk * BN;

    if (tid < 128) {
        sm[SM_W2 + tid] = W2[n_base + tid];
        sm[SM_B1 + tid] = b1[n_base + tid];
    }

    const uint32_t sbase = smem_u32(sm);

    // ---- cp.async tile loader for stage s, k-chunk kc ----
    auto load_tiles = [&](int s, int kc) {
        const int k0 = kc * KC;
        const uint32_t aw = sbase + (uint32_t)(s * STAGE_W) * 4u;
        const uint32_t bw = aw + (uint32_t)TILE_W * 4u;
#pragma unroll
        for (int j = 0; j < 2; j++) {
            int id = tid + j * 256;      // 512 chunks: 128 rows x 4
            int r  = id >> 2, c4 = (id & 3) * 4;
            int gr = m_base + r;
            if (gr > N_PATCH - 1) gr = N_PATCH - 1;
            cpa16(aw + (uint32_t)(r * KSTR + c4) * 4u, x + (size_t)gr * DIM + k0 + c4);
            cpa16(bw + (uint32_t)(r * KSTR + c4) * 4u, W1 + (size_t)(n_base + r) * DIM + k0 + c4);
        }
    };

    float acc[4][4][4];
#pragma unroll
    for (int mi = 0; mi < 4; mi++)
#pragma unroll
        for (int ni = 0; ni < 4; ni++)
#pragma unroll
            for (int q = 0; q < 4; q++) acc[mi][ni][q] = 0.f;

    load_tiles(0, 0);
    asm volatile("cp.async.commit_group;");

    for (int kc = 0; kc < NUM_KC; kc++) {
        const int s = kc & 1;
        if (kc + 1 < NUM_KC) {
            load_tiles(s ^ 1, kc + 1);
            asm volatile("cp.async.commit_group;");
            asm volatile("cp.async.wait_group 1;");
        } else {
            asm volatile("cp.async.wait_group 0;");
        }
        __syncthreads();

        const float* As = sm + s * STAGE_W;
        const float* Bs = As + TILE_W;

#pragma unroll
        for (int ks = 0; ks < 2; ks++) {
            const int kcol = ks * 8 + (lane & 3);
            // B frags (hi/lo)
            uint32_t bh[4][2], bl[4][2];
#pragma unroll
            for (int ni = 0; ni < 4; ni++) {
                int nrow = warpN * 32 + ni * 8 + (lane >> 2);
                split2(Bs[nrow * KSTR + kcol],     bh[ni][0], bl[ni][0]);
                split2(Bs[nrow * KSTR + kcol + 4], bh[ni][1], bl[ni][1]);
            }
#pragma unroll
            for (int mi = 0; mi < 4; mi++) {
                int mrow = warpM * 64 + mi * 16 + (lane >> 2);
                uint32_t ah[4], al[4];
                split2(As[mrow * KSTR + kcol],           ah[0], al[0]);
                split2(As[(mrow + 8) * KSTR + kcol],     ah[1], al[1]);
                split2(As[mrow * KSTR + kcol + 4],       ah[2], al[2]);
                split2(As[(mrow + 8) * KSTR + kcol + 4], ah[3], al[3]);
#pragma unroll
                for (int ni = 0; ni < 4; ni++)
                    mma_tf32(acc[mi][ni], ah[0], ah[1], ah[2], ah[3], bh[ni][0], bh[ni][1]);
#pragma unroll
                for (int ni = 0; ni < 4; ni++)
                    mma_tf32(acc[mi][ni], ah[0], ah[1], ah[2], ah[3], bl[ni][0], bl[ni][1]);
#pragma unroll
                for (int ni = 0; ni < 4; ni++)
                    mma_tf32(acc[mi][ni], al[0], al[1], al[2], al[3], bh[ni][0], bh[ni][1]);
            }
        }
        __syncthreads();
    }

    // ---- epilogue: tanh + W2 reduce ----
    float* red = sm + SM_RED;
#pragma unroll
    for (int mi = 0; mi < 4; mi++) {
        float p0 = 0.f, p1 = 0.f;
#pragma unroll
        for (int ni = 0; ni < 4; ni++) {
            int n0 = warpN * 32 + ni * 8 + (lane & 3) * 2;
            float w0 = sm[SM_W2 + n0],     bb0 = sm[SM_B1 + n0];
            float w1 = sm[SM_W2 + n0 + 1], bb1 = sm[SM_B1 + n0 + 1];
            p0 += w0 * tanhf(acc[mi][ni][0] + bb0);
            p0 += w1 * tanhf(acc[mi][ni][1] + bb1);
            p1 += w0 * tanhf(acc[mi][ni][2] + bb0);
            p1 += w1 * tanhf(acc[mi][ni][3] + bb1);
        }
        p0 += __shfl_xor_sync(0xFFFFFFFFu, p0, 1);
        p0 += __shfl_xor_sync(0xFFFFFFFFu, p0, 2);
        p1 += __shfl_xor_sync(0xFFFFFFFFu, p1, 1);
        p1 += __shfl_xor_sync(0xFFFFFFFFu, p1, 2);
        if ((lane & 3) == 0) {
            int r0 = warpM * 64 + mi * 16 + (lane >> 2);
            red[r0 * 4 + warpN]       = p0;
            red[(r0 + 8) * 4 + warpN] = p1;
        }
    }
    __syncthreads();
    if (tid < 128) {
        int row = m_base + tid;
        if (row < N_PATCH)
            g_Apart[nblk][row] = red[tid * 4] + red[tid * 4 + 1] +
                                 red[tid * 4 + 2] + red[tid * 4 + 3];
    }
}

// ---------------- Stage 1b: combine partials --------------------------------
__global__ void combine_kernel(const float* __restrict__ b2) {
    int i = blockIdx.x * 256 + threadIdx.x;
    if (i < N_PATCH)
        g_A[i] = g_Apart[0][i] + g_Apart[1][i] + g_Apart[2][i] + g_Apart[3][i] + b2[0];
}

// ---------------- Stage 2: global max --------------------------------------
__global__ void max_kernel() {
    __shared__ float red[1024];
    float m = -1e30f;
    for (int i = threadIdx.x; i < N_PATCH; i += 1024) m = fmaxf(m, g_A[i]);
    red[threadIdx.x] = m;
    __syncthreads();
    for (int o = 512; o > 0; o >>= 1) {
        if (threadIdx.x < o) red[threadIdx.x] = fmaxf(red[threadIdx.x], red[threadIdx.x + o]);
        __syncthreads();
    }
    if (threadIdx.x == 0) g_maxval = red[0];
}

// ---------------- Stage 3: radix-select threshold (k-th largest) -----------
__global__ void init_kernel() {
    int t = threadIdx.x;
    g_hist[t] = 0;
    if (t == 0) { g_prefix = 0; g_mask = 0; g_krem = KSEL; g_cand_cnt = 0; }
}

__global__ void hist_kernel(int shift) {
    __shared__ unsigned h[256];
    h[threadIdx.x] = 0;
    __syncthreads();
    const unsigned mask = g_mask, pref = g_prefix;
    for (int i = blockIdx.x * blockDim.x + threadIdx.x; i < N_PATCH;
         i += gridDim.x * blockDim.x) {
        unsigned key = f2k(g_A[i]);
        if ((key & mask) == pref) atomicAdd(&h[(key >> shift) & 255u], 1u);
    }
    __syncthreads();
    if (h[threadIdx.x]) atomicAdd(&g_hist[threadIdx.x], h[threadIdx.x]);
}

__global__ void scan_kernel(int shift) {
    if (threadIdx.x == 0) {
        int krem = g_krem;
        unsigned cum = 0;
        int sel = 0;
        for (int b = 255; b >= 0; b--) {
            unsigned hb = g_hist[b];
            cum += hb;
            if (cum >= (unsigned)krem) { sel = b; g_krem = krem - (int)(cum - hb); break; }
        }
        g_prefix |= ((unsigned)sel) << shift;
        g_mask   |= 0xFFu << shift;
    }
    __syncthreads();
    g_hist[threadIdx.x] = 0;
}

__global__ void compact_kernel() {
    const unsigned thr = g_prefix;
    for (int i = blockIdx.x * blockDim.x + threadIdx.x; i < N_PATCH;
         i += gridDim.x * blockDim.x) {
        if (f2k(g_A[i]) >= thr) {
            int p = atomicAdd(&g_cand_cnt, 1);
            if (p < CAP) g_cand_idx[p] = i;
        }
    }
}

// ---------------- Stage 4: sort candidates (val desc, idx asc) --------------
__global__ void sort_kernel() {
    int cnt = g_cand_cnt;
    if (cnt > CAP) cnt = CAP;
    for (int i = threadIdx.x; i < CAP; i += blockDim.x) {
        if (i < cnt) {
            int idx = g_cand_idx[i];
            g_skey[i] = ((unsigned long long)f2k(g_A[idx]) << 32) |
                        (unsigned long long)(0xFFFFFFFFu - (unsigned)idx);
        } else {
            g_skey[i] = 0ull;
        }
    }
    __syncthreads();
    for (int k = 2; k <= CAP; k <<= 1) {
        for (int j = k >> 1; j > 0; j >>= 1) {
            for (int i = threadIdx.x; i < CAP; i += blockDim.x) {
                int ixj = i ^ j;
                if (ixj > i) {
                    unsigned long long va = g_skey[i], vb = g_skey[ixj];
                    bool up = ((i & k) == 0);
                    if (up ? (va < vb) : (va > vb)) { g_skey[i] = vb; g_skey[ixj] = va; }
                }
            }
            __syncthreads();
        }
    }
    for (int i = threadIdx.x; i < KSEL; i += blockDim.x)
        g_top_idx[i] = (int)(0xFFFFFFFFu - (unsigned)(g_skey[i] & 0xFFFFFFFFull));
}

// ---------------- Stage 5: Ak = exp(A-max)/sum_topk ------------------------
__global__ void expnorm_kernel(float* __restrict__ out) {
    __shared__ float red[1024];
    const float mx = g_maxval;
    float p = 0.f;
    for (int i = threadIdx.x; i < KSEL; i += 1024)
        p += expf(g_A[g_top_idx[i]] - mx);
    red[threadIdx.x] = p;
    __syncthreads();
    for (int o = 512; o > 0; o >>= 1) {
        if (threadIdx.x < o) red[threadIdx.x] += red[threadIdx.x + o];
        __syncthreads();
    }
    const float S = red[0];
    for (int i = threadIdx.x; i < KSEL; i += 1024) {
        float ak = expf(g_A[g_top_idx[i]] - mx) / S;
        g_ak[i] = ak;
        out[DIM + i] = ak;
    }
}

// ---------------- Stage 6: M = sum Ak_i * x[idx_i] (deterministic) ----------
__global__ void wsum_kernel(const float* __restrict__ x) {
    int col = blockIdx.x * 256 + threadIdx.x;
    int r0  = blockIdx.y;
    float acc = 0.f;
    for (int r = r0; r < KSEL; r += 32)
        acc += g_ak[r] * x[(size_t)g_top_idx[r] * DIM + col];
    g_partial[r0 * DIM + col] = acc;
}

__global__ void final_kernel(float* __restrict__ out) {
    int col = blockIdx.x * 256 + threadIdx.x;
    float s = 0.f;
#pragma unroll
    for (int r = 0; r < 32; r++) s += g_partial[r * DIM + col];
    out[col] = s;
}

// ---------------- launch ----------------------------------------------------
extern "C" void kernel_launch(void* const* d_in, const int* in_sizes, int n_in,
                              void* d_out, int out_size)
{
    const float* x  = (const float*)d_in[0];
    const float* W1 = (const float*)d_in[1];
    const float* b1 = (const float*)d_in[2];
    const float* W2 = (const float*)d_in[3];
    const float* b2 = (const float*)d_in[4];
    float* out = (float*)d_out;
    (void)in_sizes; (void)n_in; (void)out_size;

    mma_score_kernel<<<GRID1, 256>>>(x, W1, b1, W2);
    combine_kernel<<<(N_PATCH + 255) / 256, 256>>>(b2);
    max_kernel<<<1, 1024>>>();
    init_kernel<<<1, 256>>>();
    for (int s = 24; s >= 0; s -= 8) {
        hist_kernel<<<256, 256>>>(s);
        scan_kernel<<<1, 256>>>(s);
    }
    compact_kernel<<<256, 256>>>();
    sort_kernel<<<1, 1024>>>();
    expnorm_kernel<<<1, 1024>>>(out);
    wsum_kernel<<<dim3(8, 32), 256>>>(x);
    final_kernel<<<8, 256>>>(out);
}

// round 6
// speedup vs baseline: 2.2030x; 1.2854x over previous
#include <cuda_runtime.h>
#include <cstdint>

#define N_PATCH 50000
#define DIM     2048
#define HID     512
#define KSEL    5000      // max(1, int(50000*0.1))
#define K1      5888      // guarded selection count (guard = 888)
#define CAPR    6144      // candidate capacity
#define CAP     8192      // bitonic sort width (pow2 >= CAPR)

// ---- tiling ----
#define KC     16
#define KSTR   20
#define NUM_KC (DIM / KC)                  // 128
#define BM1    128
#define MBLK   ((N_PATCH + BM1 - 1) / BM1) // 391
#define GRID_A1 (MBLK * 4)                 // 1564

#define TILE1_W  (128 * KSTR)              // 2560
#define STAGE1_W (2 * TILE1_W)             // 5120
#define SM1_RED  (2 * STAGE1_W)            // 10240
#define SM1_W2   (SM1_RED + 512)
#define SM1_B1   (SM1_W2 + 128)
#define SM1_WORDS (SM1_B1 + 128)           // 11008 words = 44032 B

#define BMR     64
#define TILER_A (64 * KSTR)                // 1280
#define TILER_B (128 * KSTR)               // 2560
#define STAGER_W (TILER_A + TILER_B)       // 3840
#define SMR_RED  (2 * STAGER_W)            // 7680
#define SMR_W2   (SMR_RED + 256)
#define SMR_B1   (SMR_W2 + 128)
#define SMR_WORDS (SMR_B1 + 128)           // 8192 words = 32768 B
#define RTILES  (CAPR / BMR)               // 96
#define GRID_R  (RTILES * 4)               // 384

// ---------------- scratch ----------------------------------------------------
__device__ float              g_Apart[4][50048];
__device__ float              g_A[N_PATCH];
__device__ unsigned           g_hist[256];
__device__ unsigned           g_prefix;
__device__ unsigned           g_mask;
__device__ int                g_krem;
__device__ int                g_cand_cnt;
__device__ int                g_cand_idx[CAPR];
__device__ float              g_Axp[4][CAPR];
__device__ float              g_Aex[CAPR];
__device__ unsigned long long g_skey[CAP];
__device__ int                g_top_idx[KSEL];
__device__ float              g_topA[KSEL];
__device__ float              g_ak[KSEL];
__device__ float              g_partial[32 * DIM];

// ---------------- helpers -----------------------------------------------------
__device__ __forceinline__ uint32_t smem_u32(const void* p) {
    uint32_t a;
    asm("{ .reg .u64 t; cvta.to.shared.u64 t, %1; cvt.u32.u64 %0, t; }" : "=r"(a) : "l"(p));
    return a;
}
__device__ __forceinline__ void cpa16(uint32_t saddr, const void* g) {
    asm volatile("cp.async.cg.shared.global [%0], [%1], 16;" :: "r"(saddr), "l"(g));
}
// pack two f32 -> f16x2 reg; vx -> lower half (k even), vy -> upper (k odd)
__device__ __forceinline__ uint32_t pk16(float vx, float vy) {
    uint32_t r;
    asm("cvt.rn.f16x2.f32 %0, %2, %1;" : "=r"(r) : "f"(vx), "f"(vy));
    return r;
}
__device__ __forceinline__ void up16(uint32_t p, float& lo, float& hi) {
    asm("{ .reg .b16 l, h; mov.b32 {l, h}, %2; cvt.f32.f16 %0, l; cvt.f32.f16 %1, h; }"
        : "=f"(lo), "=f"(hi) : "r"(p));
}
__device__ __forceinline__ void splitp(float vx, float vy, uint32_t& h, uint32_t& l) {
    h = pk16(vx, vy);
    float fx, fy;
    up16(h, fx, fy);
    l = pk16(vx - fx, vy - fy);
}
__device__ __forceinline__ void mma16(float* d, const uint32_t* a, const uint32_t* b) {
    asm volatile("mma.sync.aligned.m16n8k16.row.col.f32.f16.f16.f32 "
                 "{%0,%1,%2,%3},{%4,%5,%6,%7},{%8,%9},{%0,%1,%2,%3};"
                 : "+f"(d[0]), "+f"(d[1]), "+f"(d[2]), "+f"(d[3])
                 : "r"(a[0]), "r"(a[1]), "r"(a[2]), "r"(a[3]), "r"(b[0]), "r"(b[1]));
}
__device__ __forceinline__ unsigned f2k(float f) {
    unsigned u = __float_as_uint(f);
    return (u & 0x80000000u) ? ~u : (u | 0x80000000u);
}
__device__ __forceinline__ float k2f(unsigned k) {
    unsigned u = (k & 0x80000000u) ? (k ^ 0x80000000u) : ~k;
    return __uint_as_float(u);
}

// ---------------- Stage 1: single-pass fp16 approx scores --------------------
__global__ void __launch_bounds__(256, 2)
a1_kernel(const float* __restrict__ x,  const float* __restrict__ W1,
          const float* __restrict__ b1, const float* __restrict__ W2)
{
    __shared__ float sm[SM1_WORDS];
    const int tid = threadIdx.x, lane = tid & 31, wid = tid >> 5;
    const int warpM = wid & 1, warpN = wid >> 1;
    const int mblk = blockIdx.x >> 2, nblk = blockIdx.x & 3;
    const int m_base = mblk * BM1, n_base = nblk * 128;
    const int g = lane >> 2, c2 = (lane & 3) * 2;

    if (tid < 128) {
        sm[SM1_W2 + tid] = W2[n_base + tid];
        sm[SM1_B1 + tid] = b1[n_base + tid];
    }
    const uint32_t sbase = smem_u32(sm);

    auto load_tiles = [&](int s, int kc) {
        const int k0 = kc * KC;
        const uint32_t aw = sbase + (uint32_t)(s * STAGE1_W) * 4u;
        const uint32_t bw = aw + (uint32_t)TILE1_W * 4u;
#pragma unroll
        for (int j = 0; j < 2; j++) {
            int id = tid + j * 256;
            int r = id >> 2, c4 = (id & 3) * 4;
            int gr = m_base + r;
            if (gr > N_PATCH - 1) gr = N_PATCH - 1;
            cpa16(aw + (uint32_t)(r * KSTR + c4) * 4u, x + (size_t)gr * DIM + k0 + c4);
            cpa16(bw + (uint32_t)(r * KSTR + c4) * 4u, W1 + (size_t)(n_base + r) * DIM + k0 + c4);
        }
    };

    float acc[4][4][4];
#pragma unroll
    for (int mi = 0; mi < 4; mi++)
#pragma unroll
        for (int ni = 0; ni < 4; ni++)
#pragma unroll
            for (int q = 0; q < 4; q++) acc[mi][ni][q] = 0.f;

    load_tiles(0, 0);
    asm volatile("cp.async.commit_group;");

    for (int kc = 0; kc < NUM_KC; kc++) {
        const int s = kc & 1;
        if (kc + 1 < NUM_KC) {
            load_tiles(s ^ 1, kc + 1);
            asm volatile("cp.async.commit_group;");
            asm volatile("cp.async.wait_group 1;");
        } else {
            asm volatile("cp.async.wait_group 0;");
        }
        __syncthreads();

        const float* As = sm + s * STAGE1_W;
        const float* Bs = As + TILE1_W;

        uint32_t bf[4][2];
#pragma unroll
        for (int ni = 0; ni < 4; ni++) {
            int nrow = warpN * 32 + ni * 8 + g;
            float2 v0 = *reinterpret_cast<const float2*>(&Bs[nrow * KSTR + c2]);
            float2 v1 = *reinterpret_cast<const float2*>(&Bs[nrow * KSTR + c2 + 8]);
            bf[ni][0] = pk16(v0.x, v0.y);
            bf[ni][1] = pk16(v1.x, v1.y);
        }
#pragma unroll
        for (int mi = 0; mi < 4; mi++) {
            int mrow = warpM * 64 + mi * 16 + g;
            float2 a0 = *reinterpret_cast<const float2*>(&As[mrow * KSTR + c2]);
            float2 a1 = *reinterpret_cast<const float2*>(&As[(mrow + 8) * KSTR + c2]);
            float2 a2 = *reinterpret_cast<const float2*>(&As[mrow * KSTR + c2 + 8]);
            float2 a3 = *reinterpret_cast<const float2*>(&As[(mrow + 8) * KSTR + c2 + 8]);
            uint32_t af[4] = {pk16(a0.x, a0.y), pk16(a1.x, a1.y),
                              pk16(a2.x, a2.y), pk16(a3.x, a3.y)};
#pragma unroll
            for (int ni = 0; ni < 4; ni++) mma16(acc[mi][ni], af, bf[ni]);
        }
        __syncthreads();
    }

    // epilogue: tanh + W2 reduce
    float* red = sm + SM1_RED;
#pragma unroll
    for (int mi = 0; mi < 4; mi++) {
        float p0 = 0.f, p1 = 0.f;
#pragma unroll
        for (int ni = 0; ni < 4; ni++) {
            int n0 = warpN * 32 + ni * 8 + c2;
            float w0 = sm[SM1_W2 + n0],     bb0 = sm[SM1_B1 + n0];
            float w1 = sm[SM1_W2 + n0 + 1], bb1 = sm[SM1_B1 + n0 + 1];
            p0 += w0 * tanhf(acc[mi][ni][0] + bb0);
            p0 += w1 * tanhf(acc[mi][ni][1] + bb1);
            p1 += w0 * tanhf(acc[mi][ni][2] + bb0);
            p1 += w1 * tanhf(acc[mi][ni][3] + bb1);
        }
        p0 += __shfl_xor_sync(0xFFFFFFFFu, p0, 1);
        p0 += __shfl_xor_sync(0xFFFFFFFFu, p0, 2);
        p1 += __shfl_xor_sync(0xFFFFFFFFu, p1, 1);
        p1 += __shfl_xor_sync(0xFFFFFFFFu, p1, 2);
        if ((lane & 3) == 0) {
            int r0 = warpM * 64 + mi * 16 + g;
            red[r0 * 4 + warpN]       = p0;
            red[(r0 + 8) * 4 + warpN] = p1;
        }
    }
    __syncthreads();
    if (tid < 128) {
        int row = m_base + tid;
        if (row < N_PATCH)
            g_Apart[nblk][row] = red[tid * 4] + red[tid * 4 + 1] +
                                 red[tid * 4 + 2] + red[tid * 4 + 3];
    }
}

__global__ void combine_kernel() {
    int i = blockIdx.x * 256 + threadIdx.x;
    if (i < N_PATCH)
        g_A[i] = g_Apart[0][i] + g_Apart[1][i] + g_Apart[2][i] + g_Apart[3][i];
}

// ---------------- radix-select K1-th largest on A1 ---------------------------
__global__ void init_kernel() {
    int t = threadIdx.x;
    g_hist[t] = 0;
    if (t == 0) { g_prefix = 0; g_mask = 0; g_krem = K1; g_cand_cnt = 0; }
}

__global__ void hist_kernel(int shift) {
    __shared__ unsigned h[256];
    h[threadIdx.x] = 0;
    __syncthreads();
    const unsigned mask = g_mask, pref = g_prefix;
    for (int i = blockIdx.x * blockDim.x + threadIdx.x; i < N_PATCH;
         i += gridDim.x * blockDim.x) {
        unsigned key = f2k(g_A[i]);
        if ((key & mask) == pref) atomicAdd(&h[(key >> shift) & 255u], 1u);
    }
    __syncthreads();
    if (h[threadIdx.x]) atomicAdd(&g_hist[threadIdx.x], h[threadIdx.x]);
}

__global__ void scan_kernel(int shift) {
    if (threadIdx.x == 0) {
        int krem = g_krem;
        unsigned cum = 0;
        int sel = 0;
        for (int b = 255; b >= 0; b--) {
            unsigned hb = g_hist[b];
            cum += hb;
            if (cum >= (unsigned)krem) { sel = b; g_krem = krem - (int)(cum - hb); break; }
        }
        g_prefix |= ((unsigned)sel) << shift;
        g_mask   |= 0xFFu << shift;
    }
    __syncthreads();
    g_hist[threadIdx.x] = 0;
}

__global__ void compact_kernel() {
    const unsigned thr = g_prefix;
    for (int i = blockIdx.x * blockDim.x + threadIdx.x; i < N_PATCH;
         i += gridDim.x * blockDim.x) {
        if (f2k(g_A[i]) >= thr) {
            int p = atomicAdd(&g_cand_cnt, 1);
            if (p < CAPR) g_cand_idx[p] = i;
        }
    }
}

// ---------------- refine: exact scores for candidates (3-pass fp16) ----------
__global__ void __launch_bounds__(256, 2)
refine_kernel(const float* __restrict__ x,  const float* __restrict__ W1,
              const float* __restrict__ b1, const float* __restrict__ W2)
{
    __shared__ float sm[SMR_WORDS];
    const int tid = threadIdx.x, lane = tid & 31, wid = tid >> 5;
    const int warpM = wid & 1, warpN = wid >> 1;
    const int mtile = blockIdx.x >> 2, nblk = blockIdx.x & 3;
    const int m_base = mtile * BMR, n_base = nblk * 128;
    const int g = lane >> 2, c2 = (lane & 3) * 2;

    if (tid < 128) {
        sm[SMR_W2 + tid] = W2[n_base + tid];
        sm[SMR_B1 + tid] = b1[n_base + tid];
    }
    const uint32_t sbase = smem_u32(sm);

    // gathered row for A loader (1 float4/thread), fixed across chunks
    const int ar = tid >> 2, ac4 = (tid & 3) * 4;
    const int grow = g_cand_idx[m_base + ar];      // always in [0, N_PATCH)
    const float* axrow = x + (size_t)grow * DIM;

    auto load_tiles = [&](int s, int kc) {
        const int k0 = kc * KC;
        const uint32_t aw = sbase + (uint32_t)(s * STAGER_W) * 4u;
        const uint32_t bw = aw + (uint32_t)TILER_A * 4u;
        cpa16(aw + (uint32_t)(ar * KSTR + ac4) * 4u, axrow + k0 + ac4);
#pragma unroll
        for (int j = 0; j < 2; j++) {
            int id = tid + j * 256;
            int r = id >> 2, c4 = (id & 3) * 4;
            cpa16(bw + (uint32_t)(r * KSTR + c4) * 4u, W1 + (size_t)(n_base + r) * DIM + k0 + c4);
        }
    };

    float acc[2][4][4];
#pragma unroll
    for (int mi = 0; mi < 2; mi++)
#pragma unroll
        for (int ni = 0; ni < 4; ni++)
#pragma unroll
            for (int q = 0; q < 4; q++) acc[mi][ni][q] = 0.f;

    load_tiles(0, 0);
    asm volatile("cp.async.commit_group;");

    for (int kc = 0; kc < NUM_KC; kc++) {
        const int s = kc & 1;
        if (kc + 1 < NUM_KC) {
            load_tiles(s ^ 1, kc + 1);
            asm volatile("cp.async.commit_group;");
            asm volatile("cp.async.wait_group 1;");
        } else {
            asm volatile("cp.async.wait_group 0;");
        }
        __syncthreads();

        const float* As = sm + s * STAGER_W;
        const float* Bs = As + TILER_A;

        uint32_t bh[4][2], bl[4][2];
#pragma unroll
        for (int ni = 0; ni < 4; ni++) {
            int nrow = warpN * 32 + ni * 8 + g;
            float2 v0 = *reinterpret_cast<const float2*>(&Bs[nrow * KSTR + c2]);
            float2 v1 = *reinterpret_cast<const float2*>(&Bs[nrow * KSTR + c2 + 8]);
            splitp(v0.x, v0.y, bh[ni][0], bl[ni][0]);
            splitp(v1.x, v1.y, bh[ni][1], bl[ni][1]);
        }
#pragma unroll
        for (int mi = 0; mi < 2; mi++) {
            int mrow = warpM * 32 + mi * 16 + g;
            float2 a0 = *reinterpret_cast<const float2*>(&As[mrow * KSTR + c2]);
            float2 a1 = *reinterpret_cast<const float2*>(&As[(mrow + 8) * KSTR + c2]);
            float2 a2 = *reinterpret_cast<const float2*>(&As[mrow * KSTR + c2 + 8]);
            float2 a3 = *reinterpret_cast<const float2*>(&As[(mrow + 8) * KSTR + c2 + 8]);
            uint32_t ah[4], al[4];
            splitp(a0.x, a0.y, ah[0], al[0]);
            splitp(a1.x, a1.y, ah[1], al[1]);
            splitp(a2.x, a2.y, ah[2], al[2]);
            splitp(a3.x, a3.y, ah[3], al[3]);
#pragma unroll
            for (int ni = 0; ni < 4; ni++) mma16(acc[mi][ni], ah, bh[ni]);
#pragma unroll
            for (int ni = 0; ni < 4; ni++) mma16(acc[mi][ni], ah, bl[ni]);
#pragma unroll
            for (int ni = 0; ni < 4; ni++) mma16(acc[mi][ni], al, bh[ni]);
        }
        __syncthreads();
    }

    float* red = sm + SMR_RED;
#pragma unroll
    for (int mi = 0; mi < 2; mi++) {
        float p0 = 0.f, p1 = 0.f;
#pragma unroll
        for (int ni = 0; ni < 4; ni++) {
            int n0 = warpN * 32 + ni * 8 + c2;
            float w0 = sm[SMR_W2 + n0],     bb0 = sm[SMR_B1 + n0];
            float w1 = sm[SMR_W2 + n0 + 1], bb1 = sm[SMR_B1 + n0 + 1];
            p0 += w0 * tanhf(acc[mi][ni][0] + bb0);
            p0 += w1 * tanhf(acc[mi][ni][1] + bb1);
            p1 += w0 * tanhf(acc[mi][ni][2] + bb0);
            p1 += w1 * tanhf(acc[mi][ni][3] + bb1);
        }
        p0 += __shfl_xor_sync(0xFFFFFFFFu, p0, 1);
        p0 += __shfl_xor_sync(0xFFFFFFFFu, p0, 2);
        p1 += __shfl_xor_sync(0xFFFFFFFFu, p1, 1);
        p1 += __shfl_xor_sync(0xFFFFFFFFu, p1, 2);
        if ((lane & 3) == 0) {
            int r0 = warpM * 32 + mi * 16 + g;
            red[r0 * 4 + warpN]       = p0;
            red[(r0 + 8) * 4 + warpN] = p1;
        }
    }
    __syncthreads();
    if (tid < 64) {
        g_Axp[nblk][m_base + tid] = red[tid * 4] + red[tid * 4 + 1] +
                                    red[tid * 4 + 2] + red[tid * 4 + 3];
    }
}

__global__ void combine_ref_kernel() {
    int i = blockIdx.x * 256 + threadIdx.x;
    if (i < CAPR)
        g_Aex[i] = g_Axp[0][i] + g_Axp[1][i] + g_Axp[2][i] + g_Axp[3][i];
}

// ---------------- sort candidates by refined A (desc, idx asc) ----------------
__global__ void sort_kernel() {
    int cnt = g_cand_cnt;
    if (cnt > CAPR) cnt = CAPR;
    for (int i = threadIdx.x; i < CAP; i += blockDim.x) {
        if (i < cnt) {
            int idx = g_cand_idx[i];
            g_skey[i] = ((unsigned long long)f2k(g_Aex[i]) << 32) |
                        (unsigned long long)(0xFFFFFFFFu - (unsigned)idx);
        } else {
            g_skey[i] = 0ull;
        }
    }
    __syncthreads();
    for (int k = 2; k <= CAP; k <<= 1) {
        for (int j = k >> 1; j > 0; j >>= 1) {
            for (int i = threadIdx.x; i < CAP; i += blockDim.x) {
                int ixj = i ^ j;
                if (ixj > i) {
                    unsigned long long va = g_skey[i], vb = g_skey[ixj];
                    bool up = ((i & k) == 0);
                    if (up ? (va < vb) : (va > vb)) { g_skey[i] = vb; g_skey[ixj] = va; }
                }
            }
            __syncthreads();
        }
    }
    for (int i = threadIdx.x; i < KSEL; i += blockDim.x) {
        unsigned long long kk = g_skey[i];
        g_top_idx[i] = (int)(0xFFFFFFFFu - (unsigned)(kk & 0xFFFFFFFFull));
        g_topA[i]    = k2f((unsigned)(kk >> 32));
    }
}

// ---------------- Ak = exp(A-max)/sum_topk ------------------------------------
__global__ void expnorm_kernel(float* __restrict__ out) {
    __shared__ float red[1024];
    const float mx = g_topA[0];
    float p = 0.f;
    for (int i = threadIdx.x; i < KSEL; i += 1024)
        p += expf(g_topA[i] - mx);
    red[threadIdx.x] = p;
    __syncthreads();
    for (int o = 512; o > 0; o >>= 1) {
        if (threadIdx.x < o) red[threadIdx.x] += red[threadIdx.x + o];
        __syncthreads();
    }
    const float S = red[0];
    for (int i = threadIdx.x; i < KSEL; i += 1024) {
        float ak = expf(g_topA[i] - mx) / S;
        g_ak[i] = ak;
        out[DIM + i] = ak;
    }
}

// ---------------- M = sum Ak_i * x[idx_i] (deterministic) ---------------------
__global__ void wsum_kernel(const float* __restrict__ x) {
    int col = blockIdx.x * 256 + threadIdx.x;
    int r0  = blockIdx.y;
    float acc = 0.f;
    for (int r = r0; r < KSEL; r += 32)
        acc += g_ak[r] * x[(size_t)g_top_idx[r] * DIM + col];
    g_partial[r0 * DIM + col] = acc;
}

__global__ void final_kernel(float* __restrict__ out) {
    int col = blockIdx.x * 256 + threadIdx.x;
    float s = 0.f;
#pragma unroll
    for (int r = 0; r < 32; r++) s += g_partial[r * DIM + col];
    out[col] = s;
}

// ---------------- launch -------------------------------------------------------
extern "C" void kernel_launch(void* const* d_in, const int* in_sizes, int n_in,
                              void* d_out, int out_size)
{
    const float* x  = (const float*)d_in[0];
    const float* W1 = (const float*)d_in[1];
    const float* b1 = (const float*)d_in[2];
    const float* W2 = (const float*)d_in[3];
    float* out = (float*)d_out;
    (void)in_sizes; (void)n_in; (void)out_size;
    // b2 cancels algebraically in Ak (softmax renormalized) and M

    a1_kernel<<<GRID_A1, 256>>>(x, W1, b1, W2);
    combine_kernel<<<(N_PATCH + 255) / 256, 256>>>();
    init_kernel<<<1, 256>>>();
    for (int s = 24; s >= 0; s -= 8) {
        hist_kernel<<<256, 256>>>(s);
        scan_kernel<<<1, 256>>>(s);
    }
    compact_kernel<<<256, 256>>>();
    refine_kernel<<<GRID_R, 256>>>(x, W1, b1, W2);
    combine_ref_kernel<<<(CAPR + 255) / 256, 256>>>();
    sort_kernel<<<1, 1024>>>();
    expnorm_kernel<<<1, 1024>>>(out);
    wsum_kernel<<<dim3(8, 32), 256>>>(x);
    final_kernel<<<8, 256>>>(out);
}

// round 8
// speedup vs baseline: 3.4246x; 1.5545x over previous
#include <cuda_runtime.h>
#include <cstdint>

#define N_PATCH 50000
#define DIM     2048
#define HID     512
#define KSEL    5000
#define K1      5888      // guarded selection count
#define CAPR    6144
#define CAP     8192      // bitonic width

// ---- a1 tiling (fp16 inputs, KC=32, 3-stage) ----
#define KC      32
#define NUM_KC  (DIM / KC)                 // 64
#define BM1     128
#define MBLK    ((N_PATCH + BM1 - 1) / BM1)  // 391
#define GRID_A1 (MBLK * 4)                   // 1564
#define A1_ROWB 80                           // 32 halfs + 8 pad = 80 B (20 words)
#define A1_TILE_B (128 * A1_ROWB)            // 10240 B
#define A1_STG_W  (2 * A1_TILE_B / 4)        // 5120 words per stage (A+B)
#define A1_RED    (3 * A1_STG_W)             // 15360
#define A1_W2     (A1_RED + 512)
#define A1_B1     (A1_W2 + 128)
#define A1_SMEMB  ((A1_B1 + 128) * 4)        // 64512 B

// ---- refine tiling (f32 inputs, KC=32, 3-stage) ----
#define BMR     64
#define KSTR32  36                           // 32 f32 + 4 pad words
#define R_TA_W  (64 * KSTR32)                // 2304 words
#define R_TB_W  (128 * KSTR32)               // 4608 words
#define R_STG_W (R_TA_W + R_TB_W)            // 6912
#define R_RED   (3 * R_STG_W)                // 20736
#define R_W2    (R_RED + 256)
#define R_B1    (R_W2 + 128)
#define R_SMEMB ((R_B1 + 128) * 4)           // 84992 B
#define RTILES  (CAPR / BMR)                 // 96
#define GRID_R  (RTILES * 4)                 // 384

// ---------------- scratch (fp16 stored as raw u16 — no cuda_fp16.h needed) ----
__device__ uint16_t           g_xh[(size_t)N_PATCH * DIM];
__device__ uint16_t           g_w1h[HID * DIM];
__device__ float              g_Apart[4][50048];
__device__ float              g_A[N_PATCH];
__device__ unsigned           g_hist[256];
__device__ unsigned           g_prefix;
__device__ unsigned           g_mask;
__device__ int                g_krem;
__device__ int                g_cand_cnt;
__device__ int                g_cand_idx[CAPR];
__device__ float              g_Axp[4][CAPR];
__device__ float              g_Aex[CAPR];
__device__ unsigned long long g_skey[CAP];
__device__ int                g_top_idx[KSEL];
__device__ float              g_topA[KSEL];
__device__ float              g_ak[KSEL];
__device__ float              g_partial[32 * DIM];

// ---------------- helpers -----------------------------------------------------
__device__ __forceinline__ uint32_t smem_u32(const void* p) {
    uint32_t a;
    asm("{ .reg .u64 t; cvta.to.shared.u64 t, %1; cvt.u32.u64 %0, t; }" : "=r"(a) : "l"(p));
    return a;
}
__device__ __forceinline__ void cpa16(uint32_t saddr, const void* g) {
    asm volatile("cp.async.cg.shared.global [%0], [%1], 16;" :: "r"(saddr), "l"(g));
}
__device__ __forceinline__ uint32_t pk16(float vx, float vy) {
    uint32_t r;
    asm("cvt.rn.f16x2.f32 %0, %2, %1;" : "=r"(r) : "f"(vx), "f"(vy));
    return r;
}
__device__ __forceinline__ void up16(uint32_t p, float& lo, float& hi) {
    asm("{ .reg .b16 l, h; mov.b32 {l, h}, %2; cvt.f32.f16 %0, l; cvt.f32.f16 %1, h; }"
        : "=f"(lo), "=f"(hi) : "r"(p));
}
__device__ __forceinline__ void splitp(float vx, float vy, uint32_t& h, uint32_t& l) {
    h = pk16(vx, vy);
    float fx, fy;
    up16(h, fx, fy);
    l = pk16(vx - fx, vy - fy);
}
__device__ __forceinline__ void mma16(float* d, const uint32_t* a, const uint32_t* b) {
    asm volatile("mma.sync.aligned.m16n8k16.row.col.f32.f16.f16.f32 "
                 "{%0,%1,%2,%3},{%4,%5,%6,%7},{%8,%9},{%0,%1,%2,%3};"
                 : "+f"(d[0]), "+f"(d[1]), "+f"(d[2]), "+f"(d[3])
                 : "r"(a[0]), "r"(a[1]), "r"(a[2]), "r"(a[3]), "r"(b[0]), "r"(b[1]));
}
__device__ __forceinline__ unsigned f2k(float f) {
    unsigned u = __float_as_uint(f);
    return (u & 0x80000000u) ? ~u : (u | 0x80000000u);
}
__device__ __forceinline__ float k2f(unsigned k) {
    unsigned u = (k & 0x80000000u) ? (k ^ 0x80000000u) : ~k;
    return __uint_as_float(u);
}
#define CP_COMMIT() asm volatile("cp.async.commit_group;")

// ---------------- prep: f32 -> f16 conversions --------------------------------
__global__ void conv_x_kernel(const float* __restrict__ x, int base) {
    int row = base + blockIdx.x;
    int t = threadIdx.x;
    const float4* src = reinterpret_cast<const float4*>(x + (size_t)row * DIM + t * 8);
    float4 v0 = src[0], v1 = src[1];
    uint4 o;
    o.x = pk16(v0.x, v0.y); o.y = pk16(v0.z, v0.w);
    o.z = pk16(v1.x, v1.y); o.w = pk16(v1.z, v1.w);
    *reinterpret_cast<uint4*>(g_xh + (size_t)row * DIM + t * 8) = o;
}
__global__ void conv_w1_kernel(const float* __restrict__ W1) {
    int row = blockIdx.x;
    int t = threadIdx.x;
    const float4* src = reinterpret_cast<const float4*>(W1 + (size_t)row * DIM + t * 8);
    float4 v0 = src[0], v1 = src[1];
    uint4 o;
    o.x = pk16(v0.x, v0.y); o.y = pk16(v0.z, v0.w);
    o.z = pk16(v1.x, v1.y); o.w = pk16(v1.z, v1.w);
    *reinterpret_cast<uint4*>(g_w1h + (size_t)row * DIM + t * 8) = o;
}
__global__ void zero_skey_kernel() {
    int i = blockIdx.x * 256 + threadIdx.x;
    if (i < CAP) g_skey[i] = 0ull;
}

// ---------------- Stage 1: fp16 approx scores (3-stage, 1 sync/chunk) ---------
__global__ void __launch_bounds__(256, 2)
a1_kernel(const float* __restrict__ b1, const float* __restrict__ W2)
{
    extern __shared__ float smf[];
    const int tid = threadIdx.x, lane = tid & 31, wid = tid >> 5;
    const int warpM = wid & 1, warpN = wid >> 1;
    const int mblk = blockIdx.x >> 2, nblk = blockIdx.x & 3;
    const int m_base = mblk * BM1, n_base = nblk * 128;
    const int g = lane >> 2, c4 = lane & 3;

    if (tid < 128) {
        smf[A1_W2 + tid] = W2[n_base + tid];
        smf[A1_B1 + tid] = b1[n_base + tid];
    }
    const uint32_t sbase = smem_u32(smf);

    // loader rows (A: 2 fixed clamped rows; B: 2 fixed rows)
    int ar0 = tid >> 2, ar1 = ar0 + 64;
    int gr0 = m_base + ar0; if (gr0 > N_PATCH - 1) gr0 = N_PATCH - 1;
    int gr1 = m_base + ar1; if (gr1 > N_PATCH - 1) gr1 = N_PATCH - 1;
    const int c8 = (tid & 3) * 8;                 // half offset within row chunk
    const uint16_t* xr0 = g_xh + (size_t)gr0 * DIM + c8;
    const uint16_t* xr1 = g_xh + (size_t)gr1 * DIM + c8;
    const uint16_t* wr0 = g_w1h + (size_t)(n_base + ar0) * DIM + c8;
    const uint16_t* wr1 = g_w1h + (size_t)(n_base + ar1) * DIM + c8;
    const uint32_t sa0 = (uint32_t)(ar0 * A1_ROWB + (tid & 3) * 16);
    const uint32_t sa1 = (uint32_t)(ar1 * A1_ROWB + (tid & 3) * 16);

    auto load_tiles = [&](int kc) {
        const int s = kc % 3;
        const int k0 = kc * KC;
        const uint32_t aw = sbase + (uint32_t)s * (A1_STG_W * 4u);
        const uint32_t bw = aw + A1_TILE_B;
        cpa16(aw + sa0, xr0 + k0);
        cpa16(aw + sa1, xr1 + k0);
        cpa16(bw + sa0, wr0 + k0);
        cpa16(bw + sa1, wr1 + k0);
    };

    float acc[4][4][4];
#pragma unroll
    for (int mi = 0; mi < 4; mi++)
#pragma unroll
        for (int ni = 0; ni < 4; ni++)
#pragma unroll
            for (int q = 0; q < 4; q++) acc[mi][ni][q] = 0.f;

    load_tiles(0); CP_COMMIT();
    load_tiles(1); CP_COMMIT();

    for (int kc = 0; kc < NUM_KC; kc++) {
        const int s = kc % 3;
        if (kc < NUM_KC - 1) asm volatile("cp.async.wait_group 1;");
        else                 asm volatile("cp.async.wait_group 0;");
        __syncthreads();
        if (kc + 2 < NUM_KC) { load_tiles(kc + 2); CP_COMMIT(); }

        const uint32_t* As = reinterpret_cast<const uint32_t*>(smf) + s * A1_STG_W;
        const uint32_t* Bs = As + (A1_TILE_B / 4);

#pragma unroll
        for (int ks = 0; ks < 2; ks++) {
            const int ko = ks * 8 + c4;
            uint32_t bf[4][2];
#pragma unroll
            for (int ni = 0; ni < 4; ni++) {
                int nrow = warpN * 32 + ni * 8 + g;
                bf[ni][0] = Bs[nrow * 20 + ko];
                bf[ni][1] = Bs[nrow * 20 + ko + 4];
            }
#pragma unroll
            for (int mi = 0; mi < 4; mi++) {
                int mrow = warpM * 64 + mi * 16 + g;
                uint32_t af[4];
                af[0] = As[mrow * 20 + ko];
                af[1] = As[(mrow + 8) * 20 + ko];
                af[2] = As[mrow * 20 + ko + 4];
                af[3] = As[(mrow + 8) * 20 + ko + 4];
#pragma unroll
                for (int ni = 0; ni < 4; ni++) mma16(acc[mi][ni], af, bf[ni]);
            }
        }
    }
    __syncthreads();

    // epilogue: tanh + W2 reduce
    float* red = smf + A1_RED;
    const int c2 = c4 * 2;
#pragma unroll
    for (int mi = 0; mi < 4; mi++) {
        float p0 = 0.f, p1 = 0.f;
#pragma unroll
        for (int ni = 0; ni < 4; ni++) {
            int n0 = warpN * 32 + ni * 8 + c2;
            float w0 = smf[A1_W2 + n0],     bb0 = smf[A1_B1 + n0];
            float w1 = smf[A1_W2 + n0 + 1], bb1 = smf[A1_B1 + n0 + 1];
            p0 += w0 * tanhf(acc[mi][ni][0] + bb0);
            p0 += w1 * tanhf(acc[mi][ni][1] + bb1);
            p1 += w0 * tanhf(acc[mi][ni][2] + bb0);
            p1 += w1 * tanhf(acc[mi][ni][3] + bb1);
        }
        p0 += __shfl_xor_sync(0xFFFFFFFFu, p0, 1);
        p0 += __shfl_xor_sync(0xFFFFFFFFu, p0, 2);
        p1 += __shfl_xor_sync(0xFFFFFFFFu, p1, 1);
        p1 += __shfl_xor_sync(0xFFFFFFFFu, p1, 2);
        if (c4 == 0) {
            int r0 = warpM * 64 + mi * 16 + g;
            red[r0 * 4 + warpN]       = p0;
            red[(r0 + 8) * 4 + warpN] = p1;
        }
    }
    __syncthreads();
    if (tid < 128) {
        int row = m_base + tid;
        if (row < N_PATCH)
            g_Apart[nblk][row] = red[tid * 4] + red[tid * 4 + 1] +
                                 red[tid * 4 + 2] + red[tid * 4 + 3];
    }
}

__global__ void combine_kernel() {
    int i = blockIdx.x * 256 + threadIdx.x;
    if (i < N_PATCH)
        g_A[i] = g_Apart[0][i] + g_Apart[1][i] + g_Apart[2][i] + g_Apart[3][i];
}

// ---------------- radix-select K1-th largest on A1 ---------------------------
__global__ void init_kernel() {
    int t = threadIdx.x;
    g_hist[t] = 0;
    if (t == 0) { g_prefix = 0; g_mask = 0; g_krem = K1; g_cand_cnt = 0; }
}
__global__ void hist_kernel(int shift) {
    __shared__ unsigned h[256];
    h[threadIdx.x] = 0;
    __syncthreads();
    const unsigned mask = g_mask, pref = g_prefix;
    for (int i = blockIdx.x * blockDim.x + threadIdx.x; i < N_PATCH;
         i += gridDim.x * blockDim.x) {
        unsigned key = f2k(g_A[i]);
        if ((key & mask) == pref) atomicAdd(&h[(key >> shift) & 255u], 1u);
    }
    __syncthreads();
    if (h[threadIdx.x]) atomicAdd(&g_hist[threadIdx.x], h[threadIdx.x]);
}
__global__ void scan_kernel(int shift) {
    if (threadIdx.x == 0) {
        int krem = g_krem;
        unsigned cum = 0;
        int sel = 0;
        for (int b = 255; b >= 0; b--) {
            unsigned hb = g_hist[b];
            cum += hb;
            if (cum >= (unsigned)krem) { sel = b; g_krem = krem - (int)(cum - hb); break; }
        }
        g_prefix |= ((unsigned)sel) << shift;
        g_mask   |= 0xFFu << shift;
    }
    __syncthreads();
    g_hist[threadIdx.x] = 0;
}
__global__ void compact_kernel() {
    const unsigned thr = g_prefix;
    for (int i = blockIdx.x * blockDim.x + threadIdx.x; i < N_PATCH;
         i += gridDim.x * blockDim.x) {
        if (f2k(g_A[i]) >= thr) {
            int p = atomicAdd(&g_cand_cnt, 1);
            if (p < CAPR) g_cand_idx[p] = i;
        }
    }
}

// ---------------- refine: exact 3-pass fp16 for candidates --------------------
__global__ void __launch_bounds__(256, 2)
refine_kernel(const float* __restrict__ x,  const float* __restrict__ W1,
              const float* __restrict__ b1, const float* __restrict__ W2)
{
    extern __shared__ float smf[];
    const int tid = threadIdx.x, lane = tid & 31, wid = tid >> 5;
    const int warpM = wid & 1, warpN = wid >> 1;
    const int mtile = blockIdx.x >> 2, nblk = blockIdx.x & 3;
    const int m_base = mtile * BMR, n_base = nblk * 128;
    const int g = lane >> 2, c2 = (lane & 3) * 2;

    if (tid < 128) {
        smf[R_W2 + tid] = W2[n_base + tid];
        smf[R_B1 + tid] = b1[n_base + tid];
    }
    const uint32_t sbase = smem_u32(smf);

    // A loader: 2 fixed gathered rows/thread; B loader: 4 fixed rows/thread
    const int lar0 = tid >> 3, lar1 = lar0 + 32;
    const int lc16 = (tid & 7) * 16;            // byte offset of 4-f32 chunk
    const float* axr0 = x + (size_t)g_cand_idx[m_base + lar0] * DIM;
    const float* axr1 = x + (size_t)g_cand_idx[m_base + lar1] * DIM;
    const float* bwr0 = W1 + (size_t)(n_base + lar0) * DIM;
    const float* bwr1 = W1 + (size_t)(n_base + lar1) * DIM;
    const float* bwr2 = W1 + (size_t)(n_base + lar0 + 64) * DIM;
    const float* bwr3 = W1 + (size_t)(n_base + lar1 + 64) * DIM;

    auto load_tiles = [&](int kc) {
        const int s = kc % 3;
        const int k0 = kc * KC;
        const uint32_t aw = sbase + (uint32_t)s * (R_STG_W * 4u);
        const uint32_t bw = aw + R_TA_W * 4u;
        const int kb = k0 + (tid & 7) * 4;
        cpa16(aw + (uint32_t)(lar0 * 144) + lc16, axr0 + kb);
        cpa16(aw + (uint32_t)(lar1 * 144) + lc16, axr1 + kb);
        cpa16(bw + (uint32_t)(lar0 * 144) + lc16, bwr0 + kb);
        cpa16(bw + (uint32_t)(lar1 * 144) + lc16, bwr1 + kb);
        cpa16(bw + (uint32_t)((lar0 + 64) * 144) + lc16, bwr2 + kb);
        cpa16(bw + (uint32_t)((lar1 + 64) * 144) + lc16, bwr3 + kb);
    };

    float acc[2][4][4];
#pragma unroll
    for (int mi = 0; mi < 2; mi++)
#pragma unroll
        for (int ni = 0; ni < 4; ni++)
#pragma unroll
            for (int q = 0; q < 4; q++) acc[mi][ni][q] = 0.f;

    load_tiles(0); CP_COMMIT();
    load_tiles(1); CP_COMMIT();

    for (int kc = 0; kc < NUM_KC; kc++) {
        const int s = kc % 3;
        if (kc < NUM_KC - 1) asm volatile("cp.async.wait_group 1;");
        else                 asm volatile("cp.async.wait_group 0;");
        __syncthreads();
        if (kc + 2 < NUM_KC) { load_tiles(kc + 2); CP_COMMIT(); }

        const float* As = smf + s * R_STG_W;
        const float* Bs = As + R_TA_W;

#pragma unroll
        for (int ks = 0; ks < 2; ks++) {
            const int ko = ks * 16 + c2;
            uint32_t bh[4][2], bl[4][2];
#pragma unroll
            for (int ni = 0; ni < 4; ni++) {
                int nrow = warpN * 32 + ni * 8 + g;
                float2 v0 = *reinterpret_cast<const float2*>(&Bs[nrow * KSTR32 + ko]);
                float2 v1 = *reinterpret_cast<const float2*>(&Bs[nrow * KSTR32 + ko + 8]);
                splitp(v0.x, v0.y, bh[ni][0], bl[ni][0]);
                splitp(v1.x, v1.y, bh[ni][1], bl[ni][1]);
            }
#pragma unroll
            for (int mi = 0; mi < 2; mi++) {
                int mrow = warpM * 32 + mi * 16 + g;
                float2 a0 = *reinterpret_cast<const float2*>(&As[mrow * KSTR32 + ko]);
                float2 a1 = *reinterpret_cast<const float2*>(&As[(mrow + 8) * KSTR32 + ko]);
                float2 a2 = *reinterpret_cast<const float2*>(&As[mrow * KSTR32 + ko + 8]);
                float2 a3 = *reinterpret_cast<const float2*>(&As[(mrow + 8) * KSTR32 + ko + 8]);
                uint32_t ah[4], al[4];
                splitp(a0.x, a0.y, ah[0], al[0]);
                splitp(a1.x, a1.y, ah[1], al[1]);
                splitp(a2.x, a2.y, ah[2], al[2]);
                splitp(a3.x, a3.y, ah[3], al[3]);
#pragma unroll
                for (int ni = 0; ni < 4; ni++) mma16(acc[mi][ni], ah, bh[ni]);
#pragma unroll
                for (int ni = 0; ni < 4; ni++) mma16(acc[mi][ni], ah, bl[ni]);
#pragma unroll
                for (int ni = 0; ni < 4; ni++) mma16(acc[mi][ni], al, bh[ni]);
            }
        }
    }
    __syncthreads();

    float* red = smf + R_RED;
#pragma unroll
    for (int mi = 0; mi < 2; mi++) {
        float p0 = 0.f, p1 = 0.f;
#pragma unroll
        for (int ni = 0; ni < 4; ni++) {
            int n0 = warpN * 32 + ni * 8 + c2;
            float w0 = smf[R_W2 + n0],     bb0 = smf[R_B1 + n0];
            float w1 = smf[R_W2 + n0 + 1], bb1 = smf[R_B1 + n0 + 1];
            p0 += w0 * tanhf(acc[mi][ni][0] + bb0);
            p0 += w1 * tanhf(acc[mi][ni][1] + bb1);
            p1 += w0 * tanhf(acc[mi][ni][2] + bb0);
            p1 += w1 * tanhf(acc[mi][ni][3] + bb1);
        }
        p0 += __shfl_xor_sync(0xFFFFFFFFu, p0, 1);
        p0 += __shfl_xor_sync(0xFFFFFFFFu, p0, 2);
        p1 += __shfl_xor_sync(0xFFFFFFFFu, p1, 1);
        p1 += __shfl_xor_sync(0xFFFFFFFFu, p1, 2);
        if ((lane & 3) == 0) {
            int r0 = warpM * 32 + mi * 16 + g;
            red[r0 * 4 + warpN]       = p0;
            red[(r0 + 8) * 4 + warpN] = p1;
        }
    }
    __syncthreads();
    if (tid < 64) {
        g_Axp[nblk][m_base + tid] = red[tid * 4] + red[tid * 4 + 1] +
                                    red[tid * 4 + 2] + red[tid * 4 + 3];
    }
}

__global__ void combine_ref_kernel() {
    int i = blockIdx.x * 256 + threadIdx.x;
    if (i < CAPR)
        g_Aex[i] = g_Axp[0][i] + g_Axp[1][i] + g_Axp[2][i] + g_Axp[3][i];
}

// ---------------- sort candidates by refined A (desc, idx asc) ----------------
__global__ void sort_kernel() {
    int cnt = g_cand_cnt;
    if (cnt > CAPR) cnt = CAPR;
    for (int i = threadIdx.x; i < CAP; i += blockDim.x) {
        if (i < cnt) {
            int idx = g_cand_idx[i];
            g_skey[i] = ((unsigned long long)f2k(g_Aex[i]) << 32) |
                        (unsigned long long)(0xFFFFFFFFu - (unsigned)idx);
        } else {
            g_skey[i] = 0ull;
        }
    }
    __syncthreads();
    for (int k = 2; k <= CAP; k <<= 1) {
        for (int j = k >> 1; j > 0; j >>= 1) {
            for (int i = threadIdx.x; i < CAP; i += blockDim.x) {
                int ixj = i ^ j;
                if (ixj > i) {
                    unsigned long long va = g_skey[i], vb = g_skey[ixj];
                    bool up = ((i & k) == 0);
                    if (up ? (va < vb) : (va > vb)) { g_skey[i] = vb; g_skey[ixj] = va; }
                }
            }
            __syncthreads();
        }
    }
    for (int i = threadIdx.x; i < KSEL; i += blockDim.x) {
        unsigned long long kk = g_skey[i];
        g_top_idx[i] = (int)(0xFFFFFFFFu - (unsigned)(kk & 0xFFFFFFFFull));
        g_topA[i]    = k2f((unsigned)(kk >> 32));
    }
}

// ---------------- Ak = exp(A-max)/sum_topk ------------------------------------
__global__ void expnorm_kernel(float* __restrict__ out) {
    __shared__ float red[1024];
    const float mx = g_topA[0];
    float p = 0.f;
    for (int i = threadIdx.x; i < KSEL; i += 1024)
        p += expf(g_topA[i] - mx);
    red[threadIdx.x] = p;
    __syncthreads();
    for (int o = 512; o > 0; o >>= 1) {
        if (threadIdx.x < o) red[threadIdx.x] += red[threadIdx.x + o];
        __syncthreads();
    }
    const float S = red[0];
    for (int i = threadIdx.x; i < KSEL; i += 1024) {
        float ak = expf(g_topA[i] - mx) / S;
        g_ak[i] = ak;
        out[DIM + i] = ak;
    }
}

// ---------------- M = sum Ak_i * x[idx_i] -------------------------------------
__global__ void wsum_kernel(const float* __restrict__ x) {
    int col = blockIdx.x * 256 + threadIdx.x;
    int r0  = blockIdx.y;
    float acc = 0.f;
    for (int r = r0; r < KSEL; r += 32)
        acc += g_ak[r] * x[(size_t)g_top_idx[r] * DIM + col];
    g_partial[r0 * DIM + col] = acc;
}
__global__ void final_kernel(float* __restrict__ out) {
    int col = blockIdx.x * 256 + threadIdx.x;
    float s = 0.f;
#pragma unroll
    for (int r = 0; r < 32; r++) s += g_partial[r * DIM + col];
    out[col] = s;
}

// ---------------- launch -------------------------------------------------------
extern "C" void kernel_launch(void* const* d_in, const int* in_sizes, int n_in,
                              void* d_out, int out_size)
{
    const float* x  = (const float*)d_in[0];
    const float* W1 = (const float*)d_in[1];
    const float* b1 = (const float*)d_in[2];
    const float* W2 = (const float*)d_in[3];
    float* out = (float*)d_out;
    (void)in_sizes; (void)n_in; (void)out_size;
    // b2 cancels in renormalized softmax -> dropped

    cudaFuncSetAttribute(a1_kernel,     cudaFuncAttributeMaxDynamicSharedMemorySize, A1_SMEMB);
    cudaFuncSetAttribute(refine_kernel, cudaFuncAttributeMaxDynamicSharedMemorySize, R_SMEMB);

    // launches 0-4 cheap -> launch #5 is a1_kernel (ncu -s 5 -c 1 captures it)
    conv_x_kernel<<<25000, 256>>>(x, 0);
    conv_x_kernel<<<25000, 256>>>(x, 25000);
    conv_w1_kernel<<<512, 256>>>(W1);
    init_kernel<<<1, 256>>>();
    zero_skey_kernel<<<32, 256>>>();

    a1_kernel<<<GRID_A1, 256, A1_SMEMB>>>(b1, W2);
    combine_kernel<<<(N_PATCH + 255) / 256, 256>>>();
    for (int s = 24; s >= 0; s -= 8) {
        hist_kernel<<<256, 256>>>(s);
        scan_kernel<<<1, 256>>>(s);
    }
    compact_kernel<<<256, 256>>>();
    refine_kernel<<<GRID_R, 256, R_SMEMB>>>(x, W1, b1, W2);
    combine_ref_kernel<<<(CAPR + 255) / 256, 256>>>();
    sort_kernel<<<1, 1024>>>();
    expnorm_kernel<<<1, 1024>>>(out);
    wsum_kernel<<<dim3(8, 32), 256>>>(x);
    final_kernel<<<8, 256>>>(out);
}